// round 1
// baseline (speedup 1.0000x reference)
#include <cuda_runtime.h>
#include <math.h>

#define B_BATCH 4
#define T_SEQ   4096
#define C_DIM   1024
#define HSZ     128

// Scratch: projections (allowed: __device__ globals, no runtime alloc)
__device__ float g_q [B_BATCH * T_SEQ * HSZ];   // [b][t][h]
__device__ float g_kt[B_BATCH * HSZ * T_SEQ];   // [b][h][t]  (transposed K)
__device__ float g_v [B_BATCH * T_SEQ * HSZ];   // [b][t][h]

// ---------------------------------------------------------------------------
// Projection GEMM: out = x @ W   (x: [16384,1024], W: [1024,128])
// blockIdx.x: row tile (64 rows), blockIdx.y: which matrix (0=Q,1=K,2=V)
// ---------------------------------------------------------------------------
__global__ __launch_bounds__(256) void proj_kernel(
    const float* __restrict__ x,
    const float* __restrict__ Wq,
    const float* __restrict__ Wk,
    const float* __restrict__ Wv)
{
    __shared__ float xsh[64][33];     // padded to dodge bank conflicts
    __shared__ float wsh[32][HSZ];

    const int mat  = blockIdx.y;
    const float* __restrict__ W = (mat == 0) ? Wq : (mat == 1 ? Wk : Wv);
    const int row0 = blockIdx.x * 64;
    const int tid  = threadIdx.x;

    const int r0 = (tid >> 4) * 4;    // 0..60
    const int h0 = (tid & 15) * 8;    // 0..120

    float acc[4][8];
#pragma unroll
    for (int i = 0; i < 4; i++)
#pragma unroll
        for (int j = 0; j < 8; j++) acc[i][j] = 0.f;

    for (int kc = 0; kc < C_DIM; kc += 32) {
        // x tile 64x32 (float4 loads from global, scalar stores to padded smem)
        {
            const int rr = tid >> 2;
            const int cc = (tid & 3) * 8;
            const float4* src = reinterpret_cast<const float4*>(
                x + (size_t)(row0 + rr) * C_DIM + kc + cc);
            float4 a = src[0], b = src[1];
            xsh[rr][cc + 0] = a.x; xsh[rr][cc + 1] = a.y;
            xsh[rr][cc + 2] = a.z; xsh[rr][cc + 3] = a.w;
            xsh[rr][cc + 4] = b.x; xsh[rr][cc + 5] = b.y;
            xsh[rr][cc + 6] = b.z; xsh[rr][cc + 7] = b.w;
        }
        // W tile 32x128
        {
            const int kk = tid >> 4;          // 0..15 (two halves)
            const int hh = (tid & 15) * 8;
#pragma unroll
            for (int half = 0; half < 2; half++) {
                const float4* src = reinterpret_cast<const float4*>(
                    W + (size_t)(kc + kk + half * 16) * HSZ + hh);
                float4 a = src[0], b = src[1];
                float* dst = &wsh[kk + half * 16][hh];
                dst[0] = a.x; dst[1] = a.y; dst[2] = a.z; dst[3] = a.w;
                dst[4] = b.x; dst[5] = b.y; dst[6] = b.z; dst[7] = b.w;
            }
        }
        __syncthreads();

#pragma unroll
        for (int k = 0; k < 32; k++) {
            float xv[4], wv[8];
#pragma unroll
            for (int i = 0; i < 4; i++) xv[i] = xsh[r0 + i][k];
#pragma unroll
            for (int j = 0; j < 8; j++) wv[j] = wsh[k][h0 + j];
#pragma unroll
            for (int i = 0; i < 4; i++)
#pragma unroll
                for (int j = 0; j < 8; j++) acc[i][j] = fmaf(xv[i], wv[j], acc[i][j]);
        }
        __syncthreads();
    }

#pragma unroll
    for (int i = 0; i < 4; i++) {
        const int n = row0 + r0 + i;
        if (mat == 0) {
            float* dst = g_q + (size_t)n * HSZ + h0;
#pragma unroll
            for (int j = 0; j < 8; j++) dst[j] = acc[i][j];
        } else if (mat == 2) {
            float* dst = g_v + (size_t)n * HSZ + h0;
#pragma unroll
            for (int j = 0; j < 8; j++) dst[j] = acc[i][j];
        } else {
            const int b = n / T_SEQ, t = n % T_SEQ;
#pragma unroll
            for (int j = 0; j < 8; j++)
                g_kt[((size_t)b * HSZ + h0 + j) * T_SEQ + t] = acc[i][j];
        }
    }
}

// ---------------------------------------------------------------------------
// Flash attention, fp32 SIMT.
// Block: 256 threads, 64 query rows, 64-col K/V tiles, online softmax.
// Thread map: rg = tid>>4 owns 4 rows (r0=rg*4); cg = tid&15 owns
//   - 4 score cols (c0=cg*4) during QK^T
//   - 8 output dims (h0=cg*8) during PV
// m/l replicated across each 16-lane group via butterfly shuffles.
// ---------------------------------------------------------------------------
#define QSH_STRIDE 132
#define PSH_STRIDE 68

__global__ __launch_bounds__(256) void attn_kernel(float* __restrict__ out)
{
    extern __shared__ float sm[];
    float* Qsh  = sm;                                  // 64  x 132
    float* KshT = Qsh  + 64 * QSH_STRIDE;              // 128 x 64   [h][c]
    float* Vsh  = KshT + 128 * 64;                     // 64  x 128  [c][h]
    float* Psh  = Vsh  + 64 * 128;                     // 64  x 68

    const int b   = blockIdx.y;
    const int qt  = (gridDim.x - 1) - blockIdx.x;      // longest blocks first
    const int row0 = qt * 64;
    const int tid = threadIdx.x;

    const int r0 = (tid >> 4) * 4;
    const int cg = tid & 15;
    const int c0 = cg * 4;
    const int h0 = cg * 8;

    // Load Q tile (64 x 128) into smem
    {
        const int rr = tid >> 2;
        const int cc = (tid & 3) * 32;
        const float4* src = reinterpret_cast<const float4*>(
            g_q + ((size_t)(b * T_SEQ + row0 + rr)) * HSZ + cc);
#pragma unroll
        for (int u = 0; u < 8; u++) {
            float4 v = src[u];
            float* dst = &Qsh[rr * QSH_STRIDE + cc + u * 4];
            dst[0] = v.x; dst[1] = v.y; dst[2] = v.z; dst[3] = v.w;
        }
    }

    float m[4], l[4], O[4][8];
#pragma unroll
    for (int i = 0; i < 4; i++) {
        m[i] = -INFINITY; l[i] = 0.f;
#pragma unroll
        for (int j = 0; j < 8; j++) O[i][j] = 0.f;
    }

    const float scale = 0.03125f;   // C^-0.5 = 1/32

    for (int kt = 0; kt <= qt; kt++) {
        __syncthreads();   // protect K/V/P smem from previous iteration readers
        // Load K^T tile: KshT[h][c] = g_kt[b][h][kt*64+c]
        {
            const int hh = tid >> 1;
            const int cc = (tid & 1) * 32;
            const float4* src = reinterpret_cast<const float4*>(
                g_kt + ((size_t)(b * HSZ + hh)) * T_SEQ + kt * 64 + cc);
            float* dst = &KshT[hh * 64 + cc];
#pragma unroll
            for (int u = 0; u < 8; u++) {
                float4 v = src[u];
                dst[u * 4 + 0] = v.x; dst[u * 4 + 1] = v.y;
                dst[u * 4 + 2] = v.z; dst[u * 4 + 3] = v.w;
            }
        }
        // Load V tile: Vsh[c][h]
        {
            const int ccv = tid >> 2;
            const int hh  = (tid & 3) * 32;
            const float4* src = reinterpret_cast<const float4*>(
                g_v + ((size_t)(b * T_SEQ + kt * 64 + ccv)) * HSZ + hh);
            float* dst = &Vsh[ccv * 128 + hh];
#pragma unroll
            for (int u = 0; u < 8; u++) {
                float4 v = src[u];
                dst[u * 4 + 0] = v.x; dst[u * 4 + 1] = v.y;
                dst[u * 4 + 2] = v.z; dst[u * 4 + 3] = v.w;
            }
        }
        __syncthreads();

        // S = Q @ K^T  (4x4 per thread), accumulate over h
        float s[4][4];
#pragma unroll
        for (int i = 0; i < 4; i++)
#pragma unroll
            for (int j = 0; j < 4; j++) s[i][j] = 0.f;

#pragma unroll 4
        for (int h = 0; h < HSZ; h++) {
            float4 kv = *reinterpret_cast<const float4*>(&KshT[h * 64 + c0]);
            float qv0 = Qsh[(r0 + 0) * QSH_STRIDE + h];
            float qv1 = Qsh[(r0 + 1) * QSH_STRIDE + h];
            float qv2 = Qsh[(r0 + 2) * QSH_STRIDE + h];
            float qv3 = Qsh[(r0 + 3) * QSH_STRIDE + h];
            s[0][0] = fmaf(qv0, kv.x, s[0][0]); s[0][1] = fmaf(qv0, kv.y, s[0][1]);
            s[0][2] = fmaf(qv0, kv.z, s[0][2]); s[0][3] = fmaf(qv0, kv.w, s[0][3]);
            s[1][0] = fmaf(qv1, kv.x, s[1][0]); s[1][1] = fmaf(qv1, kv.y, s[1][1]);
            s[1][2] = fmaf(qv1, kv.z, s[1][2]); s[1][3] = fmaf(qv1, kv.w, s[1][3]);
            s[2][0] = fmaf(qv2, kv.x, s[2][0]); s[2][1] = fmaf(qv2, kv.y, s[2][1]);
            s[2][2] = fmaf(qv2, kv.z, s[2][2]); s[2][3] = fmaf(qv2, kv.w, s[2][3]);
            s[3][0] = fmaf(qv3, kv.x, s[3][0]); s[3][1] = fmaf(qv3, kv.y, s[3][1]);
            s[3][2] = fmaf(qv3, kv.z, s[3][2]); s[3][3] = fmaf(qv3, kv.w, s[3][3]);
        }

        const bool diag = (kt == qt);
#pragma unroll
        for (int i = 0; i < 4; i++)
#pragma unroll
            for (int j = 0; j < 4; j++) {
                if (diag && (c0 + j) > (r0 + i)) s[i][j] = -INFINITY;
                else                             s[i][j] *= scale;
            }

        // Online softmax per row (reduce across the 16-lane column group)
#pragma unroll
        for (int i = 0; i < 4; i++) {
            float tm = fmaxf(fmaxf(s[i][0], s[i][1]), fmaxf(s[i][2], s[i][3]));
#pragma unroll
            for (int off = 1; off < 16; off <<= 1)
                tm = fmaxf(tm, __shfl_xor_sync(0xffffffffu, tm, off));
            float mn = fmaxf(m[i], tm);
            float alpha = __expf(m[i] - mn);
            float p0 = __expf(s[i][0] - mn);
            float p1 = __expf(s[i][1] - mn);
            float p2 = __expf(s[i][2] - mn);
            float p3 = __expf(s[i][3] - mn);
            float ts = p0 + p1 + p2 + p3;
#pragma unroll
            for (int off = 1; off < 16; off <<= 1)
                ts += __shfl_xor_sync(0xffffffffu, ts, off);
            l[i] = l[i] * alpha + ts;
            m[i] = mn;
#pragma unroll
            for (int j = 0; j < 8; j++) O[i][j] *= alpha;
            float* pdst = &Psh[(r0 + i) * PSH_STRIDE + c0];
            pdst[0] = p0; pdst[1] = p1; pdst[2] = p2; pdst[3] = p3;
        }
        __syncthreads();

        // O += P @ V  (each thread: 4 rows x 8 head dims)
#pragma unroll 2
        for (int c = 0; c < 64; c++) {
            float4 v0 = *reinterpret_cast<const float4*>(&Vsh[c * 128 + h0]);
            float4 v1 = *reinterpret_cast<const float4*>(&Vsh[c * 128 + h0 + 4]);
            float p0 = Psh[(r0 + 0) * PSH_STRIDE + c];
            float p1 = Psh[(r0 + 1) * PSH_STRIDE + c];
            float p2 = Psh[(r0 + 2) * PSH_STRIDE + c];
            float p3 = Psh[(r0 + 3) * PSH_STRIDE + c];
            O[0][0] = fmaf(p0, v0.x, O[0][0]); O[0][1] = fmaf(p0, v0.y, O[0][1]);
            O[0][2] = fmaf(p0, v0.z, O[0][2]); O[0][3] = fmaf(p0, v0.w, O[0][3]);
            O[0][4] = fmaf(p0, v1.x, O[0][4]); O[0][5] = fmaf(p0, v1.y, O[0][5]);
            O[0][6] = fmaf(p0, v1.z, O[0][6]); O[0][7] = fmaf(p0, v1.w, O[0][7]);
            O[1][0] = fmaf(p1, v0.x, O[1][0]); O[1][1] = fmaf(p1, v0.y, O[1][1]);
            O[1][2] = fmaf(p1, v0.z, O[1][2]); O[1][3] = fmaf(p1, v0.w, O[1][3]);
            O[1][4] = fmaf(p1, v1.x, O[1][4]); O[1][5] = fmaf(p1, v1.y, O[1][5]);
            O[1][6] = fmaf(p1, v1.z, O[1][6]); O[1][7] = fmaf(p1, v1.w, O[1][7]);
            O[2][0] = fmaf(p2, v0.x, O[2][0]); O[2][1] = fmaf(p2, v0.y, O[2][1]);
            O[2][2] = fmaf(p2, v0.z, O[2][2]); O[2][3] = fmaf(p2, v0.w, O[2][3]);
            O[2][4] = fmaf(p2, v1.x, O[2][4]); O[2][5] = fmaf(p2, v1.y, O[2][5]);
            O[2][6] = fmaf(p2, v1.z, O[2][6]); O[2][7] = fmaf(p2, v1.w, O[2][7]);
            O[3][0] = fmaf(p3, v0.x, O[3][0]); O[3][1] = fmaf(p3, v0.y, O[3][1]);
            O[3][2] = fmaf(p3, v0.z, O[3][2]); O[3][3] = fmaf(p3, v0.w, O[3][3]);
            O[3][4] = fmaf(p3, v1.x, O[3][4]); O[3][5] = fmaf(p3, v1.y, O[3][5]);
            O[3][6] = fmaf(p3, v1.z, O[3][6]); O[3][7] = fmaf(p3, v1.w, O[3][7]);
        }
    }

    // Final normalize + store
#pragma unroll
    for (int i = 0; i < 4; i++) {
        const float inv = 1.0f / l[i];
        float* dst = out + ((size_t)(b * T_SEQ + row0 + r0 + i)) * HSZ + h0;
#pragma unroll
        for (int j = 0; j < 8; j++) dst[j] = O[i][j] * inv;
    }
}

// ---------------------------------------------------------------------------
extern "C" void kernel_launch(void* const* d_in, const int* in_sizes, int n_in,
                              void* d_out, int out_size)
{
    const float* x  = (const float*)d_in[0];
    const float* Wq = (const float*)d_in[1];
    const float* Wk = (const float*)d_in[2];
    const float* Wv = (const float*)d_in[3];
    float* out = (float*)d_out;

    proj_kernel<<<dim3(256, 3), 256>>>(x, Wq, Wk, Wv);

    const size_t smem = (64 * QSH_STRIDE + 128 * 64 + 64 * 128 + 64 * PSH_STRIDE)
                        * sizeof(float);  // ~114 KB
    static bool attr_set = false;
    if (!attr_set) {
        cudaFuncSetAttribute(attn_kernel,
                             cudaFuncAttributeMaxDynamicSharedMemorySize,
                             (int)smem);
        attr_set = true;
    }
    attn_kernel<<<dim3(64, B_BATCH), 256, smem>>>(out);
}

// round 2
// speedup vs baseline: 3.4105x; 3.4105x over previous
#include <cuda_runtime.h>
#include <math.h>

#define B_BATCH 4
#define T_SEQ   4096
#define C_DIM   1024
#define HSZ     128

// Scratch projections (device globals: no runtime allocation)
__device__ float g_q[B_BATCH * T_SEQ * HSZ];   // [b][t][h], tf32-rounded
__device__ float g_k[B_BATCH * T_SEQ * HSZ];   // [b][t][h], tf32-rounded
__device__ float g_v[B_BATCH * T_SEQ * HSZ];   // [b][t][h], tf32-rounded

__device__ __forceinline__ unsigned f2tf(float x) {
    unsigned u;
    asm("cvt.rna.tf32.f32 %0, %1;" : "=r"(u) : "f"(x));
    return u;
}

// D += A(16x8,row) * B(8x8,col), tf32 inputs, fp32 accumulate
__device__ __forceinline__ void mma_tf32(
    float& d0, float& d1, float& d2, float& d3,
    unsigned a0, unsigned a1, unsigned a2, unsigned a3,
    unsigned b0, unsigned b1)
{
    asm volatile(
        "mma.sync.aligned.m16n8k8.row.col.f32.tf32.tf32.f32 "
        "{%0,%1,%2,%3},{%4,%5,%6,%7},{%8,%9},{%0,%1,%2,%3};"
        : "+f"(d0), "+f"(d1), "+f"(d2), "+f"(d3)
        : "r"(a0), "r"(a1), "r"(a2), "r"(a3), "r"(b0), "r"(b1));
}

// ---------------------------------------------------------------------------
// Projection: out = x @ W  (x:[16384,1024], W:[1024,128]), outputs tf32-rounded.
// Block: 256 thr (8 warps, 4x2), tile M=128 N=128, K-chunk 32.
// ---------------------------------------------------------------------------
#define XS 36    // 36 % 32 == 4  -> A-frag loads conflict-free
#define WS 136   // 136 % 32 == 8 -> B-frag loads conflict-free

__global__ __launch_bounds__(256) void proj_kernel(
    const float* __restrict__ x,
    const float* __restrict__ Wq,
    const float* __restrict__ Wk,
    const float* __restrict__ Wv)
{
    __shared__ unsigned xs[128 * XS];
    __shared__ unsigned ws[32 * WS];

    const int mat = blockIdx.y;
    const float* __restrict__ W = (mat == 0) ? Wq : (mat == 1 ? Wk : Wv);
    float* out = (mat == 0) ? g_q : (mat == 1 ? g_k : g_v);

    const int row0 = blockIdx.x * 128;
    const int tid  = threadIdx.x;
    const int lane = tid & 31, wid = tid >> 5;
    const int wm = wid >> 1, wn = wid & 1;
    const int g = lane >> 2, tg = lane & 3;

    float acc[2][8][4];
#pragma unroll
    for (int mi = 0; mi < 2; mi++)
#pragma unroll
        for (int ni = 0; ni < 8; ni++)
#pragma unroll
            for (int j = 0; j < 4; j++) acc[mi][ni][j] = 0.f;

    for (int kc = 0; kc < C_DIM; kc += 32) {
        {   // x tile 128x32 -> tf32
            const int r = tid >> 1, c = (tid & 1) * 16;
            const float4* src = reinterpret_cast<const float4*>(
                x + (size_t)(row0 + r) * C_DIM + kc + c);
#pragma unroll
            for (int i = 0; i < 4; i++) {
                float4 v = src[i];
                unsigned* d = &xs[r * XS + c + i * 4];
                d[0] = f2tf(v.x); d[1] = f2tf(v.y);
                d[2] = f2tf(v.z); d[3] = f2tf(v.w);
            }
        }
        {   // W tile 32x128 -> tf32
            const int r = tid >> 3, c = (tid & 7) * 16;
            const float4* src = reinterpret_cast<const float4*>(
                W + (size_t)(kc + r) * HSZ + c);
#pragma unroll
            for (int i = 0; i < 4; i++) {
                float4 v = src[i];
                unsigned* d = &ws[r * WS + c + i * 4];
                d[0] = f2tf(v.x); d[1] = f2tf(v.y);
                d[2] = f2tf(v.z); d[3] = f2tf(v.w);
            }
        }
        __syncthreads();

#pragma unroll
        for (int ks = 0; ks < 4; ks++) {
            const int kk = ks * 8;
            unsigned a[2][4];
#pragma unroll
            for (int mi = 0; mi < 2; mi++) {
                const int rb = wm * 32 + mi * 16;
                a[mi][0] = xs[(rb + g)     * XS + kk + tg];
                a[mi][1] = xs[(rb + 8 + g) * XS + kk + tg];
                a[mi][2] = xs[(rb + g)     * XS + kk + 4 + tg];
                a[mi][3] = xs[(rb + 8 + g) * XS + kk + 4 + tg];
            }
#pragma unroll
            for (int ni = 0; ni < 8; ni++) {
                const int cb = wn * 64 + ni * 8;
                unsigned b0 = ws[(kk + tg)     * WS + cb + g];
                unsigned b1 = ws[(kk + 4 + tg) * WS + cb + g];
#pragma unroll
                for (int mi = 0; mi < 2; mi++)
                    mma_tf32(acc[mi][ni][0], acc[mi][ni][1],
                             acc[mi][ni][2], acc[mi][ni][3],
                             a[mi][0], a[mi][1], a[mi][2], a[mi][3], b0, b1);
            }
        }
        __syncthreads();
    }

    // Epilogue: round to tf32 and store (attention consumes tf32 bit patterns)
#pragma unroll
    for (int mi = 0; mi < 2; mi++) {
#pragma unroll
        for (int ni = 0; ni < 8; ni++) {
            const int r = row0 + wm * 32 + mi * 16 + g;
            const int c = wn * 64 + ni * 8 + 2 * tg;
            float2 v0 = make_float2(__uint_as_float(f2tf(acc[mi][ni][0])),
                                    __uint_as_float(f2tf(acc[mi][ni][1])));
            float2 v1 = make_float2(__uint_as_float(f2tf(acc[mi][ni][2])),
                                    __uint_as_float(f2tf(acc[mi][ni][3])));
            *reinterpret_cast<float2*>(out + (size_t)r * HSZ + c)       = v0;
            *reinterpret_cast<float2*>(out + (size_t)(r + 8) * HSZ + c) = v1;
        }
    }
}

// ---------------------------------------------------------------------------
// Flash attention, tf32 mma. Block: 128 thr (4 warps x 16 rows), BM=64, BN=64.
// Causal tile pairing: block handles qt=pair and qt=63-pair -> 65 iters each.
// ---------------------------------------------------------------------------
#define KS 132   // 132 % 32 == 4
#define VS 136   // 136 % 32 == 8
#define PS 68    //  68 % 32 == 4

__global__ __launch_bounds__(128) void attn_kernel(float* __restrict__ out)
{
    extern __shared__ float sm[];
    float* Ksh = sm;                       // 64 x 132  [c][h]
    float* Vsh = Ksh + 64 * KS;            // 64 x 136  [c][h]
    float* Psh = Vsh + 64 * VS;            // 64 x 68   [r][c], per-warp rows

    const int b = blockIdx.y, pair = blockIdx.x;
    const int tid = threadIdx.x, lane = tid & 31, w = tid >> 5;
    const int g = lane >> 2, tg = lane & 3;
    const float scale = 0.03125f;          // C^-0.5 = 1/32

    for (int half = 0; half < 2; half++) {
        const int qt = half ? (63 - pair) : pair;
        const int row0 = qt * 64;

        // Q fragments for this warp's 16 rows (persistent in registers)
        unsigned qa[16][4];
        {
            const float* qp = g_q + ((size_t)(b * T_SEQ + row0 + w * 16)) * HSZ;
#pragma unroll
            for (int kf = 0; kf < 16; kf++) {
                const int kk = kf * 8;
                qa[kf][0] = __float_as_uint(qp[(size_t)g * HSZ + kk + tg]);
                qa[kf][1] = __float_as_uint(qp[(size_t)(g + 8) * HSZ + kk + tg]);
                qa[kf][2] = __float_as_uint(qp[(size_t)g * HSZ + kk + 4 + tg]);
                qa[kf][3] = __float_as_uint(qp[(size_t)(g + 8) * HSZ + kk + 4 + tg]);
            }
        }

        float O[16][4];
#pragma unroll
        for (int ni = 0; ni < 16; ni++)
#pragma unroll
            for (int j = 0; j < 4; j++) O[ni][j] = 0.f;
        float mA = -INFINITY, mB = -INFINITY, lA = 0.f, lB = 0.f;

        for (int kt = 0; kt <= qt; kt++) {
            __syncthreads();   // previous consumers done with Ksh/Vsh
            {   // load K,V tiles (64 x 128 each)
                const int r = tid >> 1, c = (tid & 1) * 64;
                const float4* ksrc = reinterpret_cast<const float4*>(
                    g_k + ((size_t)(b * T_SEQ + kt * 64 + r)) * HSZ + c);
                const float4* vsrc = reinterpret_cast<const float4*>(
                    g_v + ((size_t)(b * T_SEQ + kt * 64 + r)) * HSZ + c);
                float4* kd = reinterpret_cast<float4*>(Ksh + r * KS + c);
                float4* vd = reinterpret_cast<float4*>(Vsh + r * VS + c);
#pragma unroll
                for (int i = 0; i < 16; i++) { kd[i] = ksrc[i]; vd[i] = vsrc[i]; }
            }
            __syncthreads();

            // S = Q @ K^T : warp computes 16 x 64
            float s[8][4];
#pragma unroll
            for (int ni = 0; ni < 8; ni++)
#pragma unroll
                for (int j = 0; j < 4; j++) s[ni][j] = 0.f;

#pragma unroll
            for (int kf = 0; kf < 16; kf++) {
                const int kk = kf * 8;
#pragma unroll
                for (int ni = 0; ni < 8; ni++) {
                    unsigned b0 = __float_as_uint(Ksh[(ni * 8 + g) * KS + kk + tg]);
                    unsigned b1 = __float_as_uint(Ksh[(ni * 8 + g) * KS + kk + 4 + tg]);
                    mma_tf32(s[ni][0], s[ni][1], s[ni][2], s[ni][3],
                             qa[kf][0], qa[kf][1], qa[kf][2], qa[kf][3], b0, b1);
                }
            }

            // scale + causal mask
            const bool diag = (kt == qt);
            const int rA = row0 + w * 16 + g;
            const int rB = rA + 8;
            float mxA = -INFINITY, mxB = -INFINITY;
#pragma unroll
            for (int ni = 0; ni < 8; ni++) {
                const int c0 = kt * 64 + ni * 8 + 2 * tg;
                float v0 = s[ni][0] * scale, v1 = s[ni][1] * scale;
                float v2 = s[ni][2] * scale, v3 = s[ni][3] * scale;
                if (diag) {
                    if (c0     > rA) v0 = -INFINITY;
                    if (c0 + 1 > rA) v1 = -INFINITY;
                    if (c0     > rB) v2 = -INFINITY;
                    if (c0 + 1 > rB) v3 = -INFINITY;
                }
                s[ni][0] = v0; s[ni][1] = v1; s[ni][2] = v2; s[ni][3] = v3;
                mxA = fmaxf(mxA, fmaxf(v0, v1));
                mxB = fmaxf(mxB, fmaxf(v2, v3));
            }
            mxA = fmaxf(mxA, __shfl_xor_sync(0xffffffffu, mxA, 1));
            mxA = fmaxf(mxA, __shfl_xor_sync(0xffffffffu, mxA, 2));
            mxB = fmaxf(mxB, __shfl_xor_sync(0xffffffffu, mxB, 1));
            mxB = fmaxf(mxB, __shfl_xor_sync(0xffffffffu, mxB, 2));

            const float mnA = fmaxf(mA, mxA), mnB = fmaxf(mB, mxB);
            const float aA = __expf(mA - mnA), aB = __expf(mB - mnB);

            float tsA = 0.f, tsB = 0.f;
            float* prA = Psh + (w * 16 + g) * PS;
            float* prB = Psh + (w * 16 + 8 + g) * PS;
#pragma unroll
            for (int ni = 0; ni < 8; ni++) {
                float p0 = __expf(s[ni][0] - mnA);
                float p1 = __expf(s[ni][1] - mnA);
                float p2 = __expf(s[ni][2] - mnB);
                float p3 = __expf(s[ni][3] - mnB);
                tsA += p0 + p1; tsB += p2 + p3;
                const int c = ni * 8 + 2 * tg;
                *reinterpret_cast<float2*>(prA + c) =
                    make_float2(__uint_as_float(f2tf(p0)), __uint_as_float(f2tf(p1)));
                *reinterpret_cast<float2*>(prB + c) =
                    make_float2(__uint_as_float(f2tf(p2)), __uint_as_float(f2tf(p3)));
            }
            tsA += __shfl_xor_sync(0xffffffffu, tsA, 1);
            tsA += __shfl_xor_sync(0xffffffffu, tsA, 2);
            tsB += __shfl_xor_sync(0xffffffffu, tsB, 1);
            tsB += __shfl_xor_sync(0xffffffffu, tsB, 2);
            lA = lA * aA + tsA; mA = mnA;
            lB = lB * aB + tsB; mB = mnB;

#pragma unroll
            for (int ni = 0; ni < 16; ni++) {
                O[ni][0] *= aA; O[ni][1] *= aA;
                O[ni][2] *= aB; O[ni][3] *= aB;
            }
            __syncwarp();   // P visible across the warp

            // O += P @ V : warp 16 x 128
#pragma unroll
            for (int kf = 0; kf < 8; kf++) {
                const int kk = kf * 8;
                unsigned a0 = __float_as_uint(Psh[(w * 16 + g)     * PS + kk + tg]);
                unsigned a1 = __float_as_uint(Psh[(w * 16 + 8 + g) * PS + kk + tg]);
                unsigned a2 = __float_as_uint(Psh[(w * 16 + g)     * PS + kk + 4 + tg]);
                unsigned a3 = __float_as_uint(Psh[(w * 16 + 8 + g) * PS + kk + 4 + tg]);
#pragma unroll
                for (int ni = 0; ni < 16; ni++) {
                    unsigned b0 = __float_as_uint(Vsh[(kk + tg)     * VS + ni * 8 + g]);
                    unsigned b1 = __float_as_uint(Vsh[(kk + 4 + tg) * VS + ni * 8 + g]);
                    mma_tf32(O[ni][0], O[ni][1], O[ni][2], O[ni][3],
                             a0, a1, a2, a3, b0, b1);
                }
            }
        }

        // epilogue
        const float iA = 1.f / lA, iB = 1.f / lB;
        float* op = out + ((size_t)(b * T_SEQ + row0 + w * 16)) * HSZ;
#pragma unroll
        for (int ni = 0; ni < 16; ni++) {
            const int c = ni * 8 + 2 * tg;
            *reinterpret_cast<float2*>(op + (size_t)g * HSZ + c) =
                make_float2(O[ni][0] * iA, O[ni][1] * iA);
            *reinterpret_cast<float2*>(op + (size_t)(g + 8) * HSZ + c) =
                make_float2(O[ni][2] * iB, O[ni][3] * iB);
        }
    }
}

// ---------------------------------------------------------------------------
extern "C" void kernel_launch(void* const* d_in, const int* in_sizes, int n_in,
                              void* d_out, int out_size)
{
    const float* x  = (const float*)d_in[0];
    const float* Wq = (const float*)d_in[1];
    const float* Wk = (const float*)d_in[2];
    const float* Wv = (const float*)d_in[3];
    float* out = (float*)d_out;

    proj_kernel<<<dim3(128, 3), 256>>>(x, Wq, Wk, Wv);

    const size_t smem = (size_t)(64 * KS + 64 * VS + 64 * PS) * sizeof(float); // 86016
    static bool attr_set = false;
    if (!attr_set) {
        cudaFuncSetAttribute(attn_kernel,
                             cudaFuncAttributeMaxDynamicSharedMemorySize,
                             (int)smem);
        attr_set = true;
    }
    attn_kernel<<<dim3(32, B_BATCH), 128, smem>>>(out);
}